// round 6
// baseline (speedup 1.0000x reference)
#include <cuda_runtime.h>
#include <math.h>

#define NB 128
#define NL 100
#define NH 256
#define NIN 160
#define NG 1024
#define NCAP 1600
#define NCL 19
#define NOD 304
#define NCH 8

typedef unsigned long long ull;

// packed fp32x2 fma: c = a*b + c  (per-lane on the two packed floats)
#define FMA2(c,a,b) asm("fma.rn.f32x2 %0, %1, %2, %3;" : "=l"(c) : "l"(a), "l"(b), "l"(c))

__device__ __forceinline__ float unpack_sum(ull v){
    float lo, hi;
    asm("mov.b64 {%0,%1}, %2;" : "=f"(lo), "=f"(hi) : "l"(v));
    return lo + hi;
}

// ---------------- static device scratch (no allocations) ----------------
__device__ float g_emb[NL*NB*NIN];
__device__ float g_xg[2*NL*NG*NB];          // [dir][t][g][b]
__device__ float g_h[2][2][NB*NH];          // ping-pong h per dir
__device__ float g_hall[2*NL*NB*NH];        // [dir][t][b][256]
__device__ float g_x[NB*NL*NH];
__device__ float g_u[NB*NCAP*16];
__device__ float g_att[NB*NL];
__device__ float g_cbase[NCAP*NCL];
__device__ float g_uhat[(size_t)NB*NCAP*NOD];
__device__ float g_bb[(size_t)NB*NCAP*NCL];
__device__ float g_spart[NB*NCH*NOD];
__device__ float g_v[NB*NOD];
__device__ unsigned g_cnt;
__device__ unsigned g_phase;

__device__ __forceinline__ float sigm(float x){ return 1.f/(1.f+expf(-x)); }

// 1) embedding gather
__global__ void k_embed(const int* __restrict__ word,const int* __restrict__ tag,
                        const int* __restrict__ p1,const int* __restrict__ p2,
                        const float* __restrict__ we,const float* __restrict__ te,
                        const float* __restrict__ p1e,const float* __restrict__ p2e){
    int bl=blockIdx.x, t=bl/NB, b=bl%NB, d=threadIdx.x;
    float v;
    if(d<100)      v=we[(size_t)word[b*NL+t]*100+d];
    else if(d<120) v=te[tag[b*NL+t]*20+(d-100)];
    else if(d<140) v=p1e[p1[b*NL+t]*20+(d-120)];
    else           v=p2e[p2[b*NL+t]*20+(d-140)];
    g_emb[(t*NB+b)*NIN+d]=v;
}

// 2) xg = emb @ w_ih^T + b_ih + b_hh  -> [dir][t][g][b]   (f32x2 packed along k)
__global__ __launch_bounds__(256) void k_xg(
        const float* __restrict__ wih_f,const float* __restrict__ wih_b,
        const float* __restrict__ bih_f,const float* __restrict__ bhh_f,
        const float* __restrict__ bih_b,const float* __restrict__ bhh_b){
    __shared__ __align__(16) float Ws[64*18];
    __shared__ __align__(16) float Es[64*18];
    int t=blockIdx.y, dir=blockIdx.z;
    int g0=(blockIdx.x&15)*64, b0=(blockIdx.x>>4)*64;
    const float* wih=dir?wih_b:wih_f;
    const float* bih=dir?bih_b:bih_f;
    const float* bhh=dir?bhh_b:bhh_f;
    int tid=threadIdx.x, tx=tid&15, ty=tid>>4;
    ull acc2[4][4];
    #pragma unroll
    for(int i=0;i<4;i++)
        #pragma unroll
        for(int j=0;j<4;j++) acc2[i][j]=0ull;
    for(int kk=0;kk<NIN;kk+=16){
        #pragma unroll
        for(int e=tid;e<1024;e+=256){
            int r=e>>4,c=e&15;
            Ws[r*18+c]=wih[(g0+r)*NIN+kk+c];
            Es[r*18+c]=g_emb[(t*NB+b0+r)*NIN+kk+c];
        }
        __syncthreads();
        #pragma unroll
        for(int k=0;k<16;k+=2){
            ull a2[4],e2[4];
            #pragma unroll
            for(int i=0;i<4;i++) a2[i]=*(const ull*)(Ws+(ty*4+i)*18+k);
            #pragma unroll
            for(int j=0;j<4;j++) e2[j]=*(const ull*)(Es+(tx*4+j)*18+k);
            #pragma unroll
            for(int i=0;i<4;i++)
                #pragma unroll
                for(int j=0;j<4;j++) FMA2(acc2[i][j],a2[i],e2[j]);
        }
        __syncthreads();
    }
    #pragma unroll
    for(int i=0;i<4;i++){
        int g=g0+ty*4+i;
        float bias=bih[g]+bhh[g];
        float4 r4=make_float4(unpack_sum(acc2[i][0])+bias,unpack_sum(acc2[i][1])+bias,
                              unpack_sum(acc2[i][2])+bias,unpack_sum(acc2[i][3])+bias);
        *(float4*)(g_xg+((size_t)(dir*NL+t)*NG+g)*NB+b0+tx*4)=r4;
    }
}

// 3) persistent BiLSTM: 128 CTAs x 256 threads (k-split halves), f32x2 math,
//    grid-wide software barrier (one wave on 148 SMs -> co-resident)
__global__ __launch_bounds__(256,1) void k_lstm(const float* __restrict__ whh_f,
                                                const float* __restrict__ whh_b){
    __shared__ __align__(16) float sW[16*256];     // [r][k] gate rows for 4 hidden units
    __shared__ float sRed[16*128];                  // half-1 partials [r][b]
    __shared__ unsigned s_base;
    int tid=threadIdx.x, dir=blockIdx.x>>6, u0=(blockIdx.x&63)*4;
    const float* whh=dir?whh_b:whh_f;
    for(int e=tid;e<4096;e+=256){
        int r=e>>8,k=e&255;
        sW[e]=whh[((r>>2)*256+u0+(r&3))*256+k];
    }
    if(tid==0) s_base=atomicAdd(&g_phase,0u);
    __syncthreads();
    int b=tid&127, half=tid>>7, k0=half<<7;
    float c[4]={0.f,0.f,0.f,0.f};
    for(int s=0;s<NL;s++){
        int t=dir?(NL-1-s):s;
        ull acc2[16];
        #pragma unroll
        for(int r=0;r<16;r++) acc2[r]=0ull;
        if(s>0){
            const float* hrow=g_h[dir][s&1]+b*NH+k0;
            #pragma unroll 8
            for(int k=0;k<128;k+=4){
                ulonglong2 h2=__ldcg((const ulonglong2*)(hrow+k));
                #pragma unroll
                for(int r=0;r<16;r++){
                    const ulonglong2* w2=(const ulonglong2*)(sW+r*256+k0+k);
                    FMA2(acc2[r],h2.x,w2->x);
                    FMA2(acc2[r],h2.y,w2->y);
                }
            }
        }
        if(half){
            #pragma unroll
            for(int r=0;r<16;r++) sRed[r*128+b]=unpack_sum(acc2[r]);
        }
        __syncthreads();
        if(!half){
            const float* xgp=g_xg+((size_t)(dir*NL+t)*NG)*NB+b;
            float acc[16];
            #pragma unroll
            for(int r=0;r<16;r++)
                acc[r]=unpack_sum(acc2[r])+sRed[r*128+b]
                      +xgp[(size_t)((r>>2)*256+u0+(r&3))*NB];
            float* hdst=g_h[dir][(s+1)&1];
            float* hall=g_hall+((size_t)(dir*NL+t)*NB+b)*NH;
            #pragma unroll
            for(int j=0;j<4;j++){
                float cn=sigm(acc[4+j])*c[j]+sigm(acc[j])*tanhf(acc[8+j]);
                c[j]=cn;
                float hn=sigm(acc[12+j])*tanhf(cn);
                hdst[b*NH+u0+j]=hn;
                hall[u0+j]=hn;
            }
        }
        __threadfence();
        __syncthreads();
        if(tid==0){
            unsigned tgt=s_base+(unsigned)(s+1);
            if(atomicAdd(&g_cnt,1u)==127u){
                atomicExch(&g_cnt,0u);
                __threadfence();
                atomicAdd(&g_phase,1u);
            } else {
                while(*((volatile unsigned*)&g_phase) < tgt) __nanosleep(32);
            }
        }
        __syncthreads();
    }
}

// 4) x = hf + hb ; u = squash(primary caps)
__global__ __launch_bounds__(256) void k_combine(){
    int bl=blockIdx.x, b=bl/NL, l=bl%NL, j=threadIdx.x;
    float v=g_hall[((size_t)(0*NL+l)*NB+b)*NH+j]+g_hall[((size_t)(1*NL+l)*NB+b)*NH+j];
    g_x[((size_t)b*NL+l)*NH+j]=v;
    float n2=v*v;
    n2+=__shfl_xor_sync(0xffffffffu,n2,1);
    n2+=__shfl_xor_sync(0xffffffffu,n2,2);
    n2+=__shfl_xor_sync(0xffffffffu,n2,4);
    n2+=__shfl_xor_sync(0xffffffffu,n2,8);
    float f=(n2/(1.f+n2))*rsqrtf(n2+1e-9f);
    g_u[((size_t)b*NCAP+l*16)*16+j]=v*f;
}

// 5) entity gather + attention softmax over L
__global__ __launch_bounds__(256) void k_att(const int* __restrict__ pos1,
                                             const int* __restrict__ pos2){
    __shared__ int se1,se2;
    __shared__ float she[NH];
    __shared__ float sd[NL];
    int b=blockIdx.x, tid=threadIdx.x;
    if(tid<NL){
        if(pos1[b*NL+tid]==68) se1=tid;
        if(pos2[b*NL+tid]==68) se2=tid;
    }
    __syncthreads();
    she[tid]=g_x[((size_t)b*NL+se1)*NH+tid]+g_x[((size_t)b*NL+se2)*NH+tid];
    __syncthreads();
    int warp=tid>>5, lane=tid&31;
    for(int l=warp;l<NL;l+=8){
        const float* xr=g_x+((size_t)b*NL+l)*NH;
        float s=0.f;
        for(int k=lane;k<NH;k+=32) s+=xr[k]*she[k];
        for(int m=16;m;m>>=1) s+=__shfl_xor_sync(0xffffffffu,s,m);
        if(lane==0) sd[l]=s;
    }
    __syncthreads();
    if(tid<32){
        float vals[4],mx=-1e30f;
        #pragma unroll
        for(int q=0;q<4;q++){
            int l=tid+32*q;
            vals[q]=(l<NL)?sd[l]:-1e30f;
            mx=fmaxf(mx,vals[q]);
        }
        for(int m=16;m;m>>=1) mx=fmaxf(mx,__shfl_xor_sync(0xffffffffu,mx,m));
        float es[4],ss=0.f;
        #pragma unroll
        for(int q=0;q<4;q++){
            int l=tid+32*q;
            es[q]=(l<NL)?expf(vals[q]-mx):0.f;
            ss+=es[q];
        }
        for(int m=16;m;m>>=1) ss+=__shfl_xor_sync(0xffffffffu,ss,m);
        float inv=1.f/ss;
        #pragma unroll
        for(int q=0;q<4;q++){
            int l=tid+32*q;
            if(l<NL) g_att[b*NL+l]=es[q]*inv;
        }
    }
}

// 6) softmax(b_route) once (iter-0 coupling, batch-independent)
__global__ void k_cbase(const float* __restrict__ br){
    int i=blockIdx.x, lane=threadIdx.x;
    float v=(lane<NCL)?br[i*NCL+lane]:-1e30f;
    float mx=v;
    for(int m=16;m;m>>=1) mx=fmaxf(mx,__shfl_xor_sync(0xffffffffu,mx,m));
    float e=(lane<NCL)?expf(v-mx):0.f;
    float s=e;
    for(int m=16;m;m>>=1) s+=__shfl_xor_sync(0xffffffffu,s,m);
    if(lane<NCL) g_cbase[i*NCL+lane]=e/s;
}

// 7) u_hat[b][i][:] = u[b][i][:16] @ W_caps[i]   (1600 blocks)
__global__ __launch_bounds__(256) void k_uhat(const float* __restrict__ Wc){
    __shared__ float Ws[16*NOD];
    __shared__ float Ut[16*132];
    int i=blockIdx.x, tid=threadIdx.x;
    const float* wp=Wc+(size_t)i*16*NOD;
    for(int e=tid;e<16*NOD;e+=256) Ws[e]=wp[e];
    for(int e=tid;e<2048;e+=256){
        int bb_=e>>4,cc=e&15;
        Ut[cc*132+bb_]=g_u[((size_t)bb_*NCAP+i)*16+cc];
    }
    __syncthreads();
    for(int tI=tid;tI<32*76;tI+=256){
        int ot=tI%76, bt=tI/76, o0=ot*4, b0=bt*4;
        float acc[4][4];
        #pragma unroll
        for(int x=0;x<4;x++)
            #pragma unroll
            for(int y=0;y<4;y++) acc[x][y]=0.f;
        #pragma unroll
        for(int cc=0;cc<16;cc++){
            float4 u4=*(const float4*)(Ut+cc*132+b0);
            float4 w4=*(const float4*)(Ws+cc*NOD+o0);
            acc[0][0]+=u4.x*w4.x; acc[0][1]+=u4.x*w4.y; acc[0][2]+=u4.x*w4.z; acc[0][3]+=u4.x*w4.w;
            acc[1][0]+=u4.y*w4.x; acc[1][1]+=u4.y*w4.y; acc[1][2]+=u4.y*w4.z; acc[1][3]+=u4.y*w4.w;
            acc[2][0]+=u4.z*w4.x; acc[2][1]+=u4.z*w4.y; acc[2][2]+=u4.z*w4.z; acc[2][3]+=u4.z*w4.w;
            acc[3][0]+=u4.w*w4.x; acc[3][1]+=u4.w*w4.y; acc[3][2]+=u4.w*w4.z; acc[3][3]+=u4.w*w4.w;
        }
        #pragma unroll
        for(int bi=0;bi<4;bi++){
            float4 r4=make_float4(acc[bi][0],acc[bi][1],acc[bi][2],acc[bi][3]);
            *(float4*)(g_uhat+((size_t)(b0+bi)*NCAP+i)*NOD+o0)=r4;
        }
    }
}

// 8) fused routing pass: agreement of prev iter + weighted-sum of this iter
__global__ __launch_bounds__(320) void k_route(int mode,const float* __restrict__ b_route){
    __shared__ float sv[320];
    __shared__ float sag[32];
    __shared__ float sc[32];
    int tid=threadIdx.x, b=blockIdx.y, chunk=blockIdx.x;
    int o=tid>>4, d=tid&15;
    sv[tid]=(mode>0&&tid<NOD)?g_v[b*NOD+tid]:0.f;
    __syncthreads();
    int i0=chunk*(NCAP/NCH);
    float accS=0.f;
    float u=(tid<NOD)?g_uhat[((size_t)b*NCAP+i0)*NOD+tid]:0.f;
    for(int ii=0;ii<NCAP/NCH;ii++){
        int i=i0+ii;
        float unext=0.f;
        if(ii+1<NCAP/NCH&&tid<NOD)
            unext=g_uhat[((size_t)b*NCAP+i+1)*NOD+tid];
        float atti=g_att[b*NL+(i>>4)];
        float cO;
        if(mode==0){
            cO=(o<NCL)?g_cbase[i*NCL+o]*atti:0.f;
        } else {
            float p=u*sv[tid];
            p+=__shfl_xor_sync(0xffffffffu,p,1);
            p+=__shfl_xor_sync(0xffffffffu,p,2);
            p+=__shfl_xor_sync(0xffffffffu,p,4);
            p+=__shfl_xor_sync(0xffffffffu,p,8);
            if(d==0&&o<NCL){
                float prior=(mode==1)?b_route[i*NCL+o]:g_bb[((size_t)b*NCAP+i)*NCL+o];
                float nb=prior+p;
                if(mode==1) g_bb[((size_t)b*NCAP+i)*NCL+o]=nb;
                sag[o]=nb;
            }
            __syncthreads();
            if(tid<32){
                float v=(tid<NCL)?sag[tid]:-1e30f;
                float mx=v;
                for(int m=16;m;m>>=1) mx=fmaxf(mx,__shfl_xor_sync(0xffffffffu,mx,m));
                float e=(tid<NCL)?expf(v-mx):0.f;
                float ss=e;
                for(int m=16;m;m>>=1) ss+=__shfl_xor_sync(0xffffffffu,ss,m);
                if(tid<NCL) sc[tid]=e/ss*atti;
            }
            __syncthreads();
            cO=(o<NCL)?sc[o]:0.f;
        }
        accS+=cO*u;
        u=unext;
    }
    if(tid<NOD) g_spart[(b*NCH+chunk)*NOD+tid]=accS;
}

// 9) reduce partials + squash -> v (or final class lengths)
__global__ __launch_bounds__(320) void k_reduce(int final_out,float* __restrict__ out){
    int b=blockIdx.x, tid=threadIdx.x;
    float s=0.f;
    if(tid<NOD){
        #pragma unroll
        for(int ch=0;ch<NCH;ch++) s+=g_spart[(b*NCH+ch)*NOD+tid];
    }
    float n2=s*s;
    n2+=__shfl_xor_sync(0xffffffffu,n2,1);
    n2+=__shfl_xor_sync(0xffffffffu,n2,2);
    n2+=__shfl_xor_sync(0xffffffffu,n2,4);
    n2+=__shfl_xor_sync(0xffffffffu,n2,8);
    float f=(n2/(1.f+n2))*rsqrtf(n2+1e-9f);
    if(!final_out){
        if(tid<NOD) g_v[b*NOD+tid]=s*f;
    } else {
        if(tid<NOD&&(tid&15)==0)
            out[b*NCL+(tid>>4)]=sqrtf(n2*f*f+1e-9f);
    }
}

extern "C" void kernel_launch(void* const* d_in,const int* in_sizes,int n_in,
                              void* d_out,int out_size){
    (void)in_sizes;(void)n_in;(void)out_size;
    const int*   word =(const int*)d_in[0];
    const int*   tag  =(const int*)d_in[1];
    const int*   pos1 =(const int*)d_in[2];
    const int*   pos2 =(const int*)d_in[3];
    const float* we   =(const float*)d_in[4];
    const float* te   =(const float*)d_in[5];
    const float* p1e  =(const float*)d_in[6];
    const float* p2e  =(const float*)d_in[7];
    const float* wih_f=(const float*)d_in[8];
    const float* whh_f=(const float*)d_in[9];
    const float* bih_f=(const float*)d_in[10];
    const float* bhh_f=(const float*)d_in[11];
    const float* wih_b=(const float*)d_in[12];
    const float* whh_b=(const float*)d_in[13];
    const float* bih_b=(const float*)d_in[14];
    const float* bhh_b=(const float*)d_in[15];
    const float* Wc   =(const float*)d_in[16];
    const float* br   =(const float*)d_in[17];
    float* out=(float*)d_out;

    k_embed<<<NL*NB,160>>>(word,tag,pos1,pos2,we,te,p1e,p2e);
    k_cbase<<<NCAP,32>>>(br);
    k_xg<<<dim3(32,NL,2),256>>>(wih_f,wih_b,bih_f,bhh_f,bih_b,bhh_b);
    k_lstm<<<128,256>>>(whh_f,whh_b);
    k_combine<<<NB*NL,256>>>();
    k_att<<<NB,256>>>(pos1,pos2);
    k_uhat<<<NCAP,256>>>(Wc);
    k_route<<<dim3(NCH,NB),320>>>(0,br);
    k_reduce<<<NB,320>>>(0,out);
    k_route<<<dim3(NCH,NB),320>>>(1,br);
    k_reduce<<<NB,320>>>(0,out);
    k_route<<<dim3(NCH,NB),320>>>(2,br);
    k_reduce<<<NB,320>>>(1,out);
}

// round 7
// speedup vs baseline: 1.3569x; 1.3569x over previous
#include <cuda_runtime.h>
#include <math.h>

#define NB 128
#define NL 100
#define NH 256
#define NIN 160
#define NG 1024
#define NCAP 1600
#define NCL 19
#define NOD 304
#define NCH 8

typedef unsigned long long ull;

// packed fp32x2 fma: c = a*b + c
#define FMA2(c,a,b) asm("fma.rn.f32x2 %0, %1, %2, %3;" : "=l"(c) : "l"(a), "l"(b), "l"(c))

__device__ __forceinline__ float unpack_sum(ull v){
    float lo, hi;
    asm("mov.b64 {%0,%1}, %2;" : "=f"(lo), "=f"(hi) : "l"(v));
    return lo + hi;
}

// ---------------- static device scratch (no allocations) ----------------
__device__ float g_emb[NL*NB*NIN];
__device__ float g_xg[2*NL*NG*NB];          // [dir][t][g][b]
__device__ float g_h[2][2][NB*NH];          // ping-pong h per dir
__device__ float g_hall[2*NL*NB*NH];        // [dir][t][b][256]
__device__ float g_x[NB*NL*NH];
__device__ float g_u[NB*NCAP*16];
__device__ float g_att[NB*NL];
__device__ float g_cbase[NCAP*NCL];
__device__ float g_uhat[(size_t)NB*NCAP*NOD];
__device__ float g_bb[(size_t)NB*NCAP*NCL];
__device__ float g_spart[NB*NCH*NOD];
__device__ float g_v[NB*NOD];
__device__ unsigned g_cnt;
__device__ unsigned g_phase;

__device__ __forceinline__ float sigm(float x){ return 1.f/(1.f+expf(-x)); }

// 1) embedding gather
__global__ void k_embed(const int* __restrict__ word,const int* __restrict__ tag,
                        const int* __restrict__ p1,const int* __restrict__ p2,
                        const float* __restrict__ we,const float* __restrict__ te,
                        const float* __restrict__ p1e,const float* __restrict__ p2e){
    int bl=blockIdx.x, t=bl/NB, b=bl%NB, d=threadIdx.x;
    float v;
    if(d<100)      v=we[(size_t)word[b*NL+t]*100+d];
    else if(d<120) v=te[tag[b*NL+t]*20+(d-100)];
    else if(d<140) v=p1e[p1[b*NL+t]*20+(d-120)];
    else           v=p2e[p2[b*NL+t]*20+(d-140)];
    g_emb[(t*NB+b)*NIN+d]=v;
}

// 2) xg = emb @ w_ih^T + b_ih + b_hh  -> [dir][t][g][b]   (R5 scalar version, known good)
__global__ __launch_bounds__(256) void k_xg(
        const float* __restrict__ wih_f,const float* __restrict__ wih_b,
        const float* __restrict__ bih_f,const float* __restrict__ bhh_f,
        const float* __restrict__ bih_b,const float* __restrict__ bhh_b){
    __shared__ float Ws[64*17];
    __shared__ float Es[64*17];
    int t=blockIdx.y, dir=blockIdx.z;
    int g0=(blockIdx.x&15)*64, b0=(blockIdx.x>>4)*64;
    const float* wih=dir?wih_b:wih_f;
    const float* bih=dir?bih_b:bih_f;
    const float* bhh=dir?bhh_b:bhh_f;
    int tid=threadIdx.x, tx=tid&15, ty=tid>>4;
    float acc[4][4];
    #pragma unroll
    for(int i=0;i<4;i++)
        #pragma unroll
        for(int j=0;j<4;j++) acc[i][j]=0.f;
    for(int kk=0;kk<NIN;kk+=16){
        #pragma unroll
        for(int e=tid;e<1024;e+=256){
            int r=e>>4,c=e&15;
            Ws[r*17+c]=wih[(g0+r)*NIN+kk+c];
            Es[r*17+c]=g_emb[(t*NB+b0+r)*NIN+kk+c];
        }
        __syncthreads();
        #pragma unroll
        for(int k=0;k<16;k++){
            float a[4],eb[4];
            #pragma unroll
            for(int i=0;i<4;i++) a[i]=Ws[(ty*4+i)*17+k];
            #pragma unroll
            for(int j=0;j<4;j++) eb[j]=Es[(tx*4+j)*17+k];
            #pragma unroll
            for(int i=0;i<4;i++)
                #pragma unroll
                for(int j=0;j<4;j++) acc[i][j]+=a[i]*eb[j];
        }
        __syncthreads();
    }
    #pragma unroll
    for(int i=0;i<4;i++){
        int g=g0+ty*4+i;
        float bias=bih[g]+bhh[g];
        float4 r4=make_float4(acc[i][0]+bias,acc[i][1]+bias,acc[i][2]+bias,acc[i][3]+bias);
        *(float4*)(g_xg+((size_t)(dir*NL+t)*NG+g)*NB+b0+tx*4)=r4;
    }
}

// 3) persistent BiLSTM: 256 CTAs x 128 threads (2 CTAs/SM, 2 hidden units/CTA),
//    f32x2 math, 8-deep LDG prefetch of h, grid barrier with 256 arrivals.
//    No intra-step syncs beyond the barrier pair (the R6 mistake removed).
__global__ __launch_bounds__(128,2) void k_lstm(const float* __restrict__ whh_f,
                                                const float* __restrict__ whh_b){
    __shared__ __align__(16) float sW[8*256];   // 8 gate rows: (gate=r>>1, unit=u0+(r&1))
    __shared__ unsigned s_base;
    int tid=threadIdx.x;
    int dir=blockIdx.x>>7;                      // 0..127 -> dir0, 128..255 -> dir1
    int u0=(blockIdx.x&127)*2;
    const float* whh=dir?whh_b:whh_f;
    for(int e=tid;e<2048;e+=128){
        int r=e>>8,k=e&255;
        sW[e]=whh[((r>>1)*256+u0+(r&1))*256+k];
    }
    if(tid==0) s_base=atomicAdd(&g_phase,0u);
    __syncthreads();
    int b=tid;
    float cst[2]={0.f,0.f};
    for(int s=0;s<NL;s++){
        int t=dir?(NL-1-s):s;
        ull acc2[8]={0,0,0,0,0,0,0,0};
        if(s>0){
            const float* hrow=g_h[dir][s&1]+b*NH;
            for(int kc=0;kc<256;kc+=32){
                ulonglong2 hbuf[8];
                #pragma unroll
                for(int q=0;q<8;q++)
                    hbuf[q]=__ldcg((const ulonglong2*)(hrow+kc+q*4));   // 8 LDG.128 in flight
                #pragma unroll
                for(int q=0;q<8;q++){
                    #pragma unroll
                    for(int r=0;r<8;r++){
                        const ulonglong2* w2=(const ulonglong2*)(sW+r*256+kc+q*4);
                        FMA2(acc2[r],hbuf[q].x,w2->x);
                        FMA2(acc2[r],hbuf[q].y,w2->y);
                    }
                }
            }
        }
        const float* xgp=g_xg+((size_t)(dir*NL+t)*NG)*NB+b;
        float acc[8];
        #pragma unroll
        for(int r=0;r<8;r++)
            acc[r]=unpack_sum(acc2[r])+xgp[(size_t)((r>>1)*256+u0+(r&1))*NB];
        float* hdst=g_h[dir][(s+1)&1];
        float* hall=g_hall+((size_t)(dir*NL+t)*NB+b)*NH;
        #pragma unroll
        for(int j=0;j<2;j++){
            float cn=sigm(acc[2+j])*cst[j]+sigm(acc[j])*tanhf(acc[4+j]);
            cst[j]=cn;
            float hn=sigm(acc[6+j])*tanhf(cn);
            hdst[b*NH+u0+j]=hn;
            hall[u0+j]=hn;
        }
        __threadfence();
        __syncthreads();
        if(tid==0){
            unsigned tgt=s_base+(unsigned)(s+1);
            if(atomicAdd(&g_cnt,1u)==255u){
                atomicExch(&g_cnt,0u);
                __threadfence();
                atomicAdd(&g_phase,1u);
            } else {
                while(*((volatile unsigned*)&g_phase) < tgt) __nanosleep(32);
            }
        }
        __syncthreads();
    }
}

// 4) x = hf + hb ; u = squash(primary caps)
__global__ __launch_bounds__(256) void k_combine(){
    int bl=blockIdx.x, b=bl/NL, l=bl%NL, j=threadIdx.x;
    float v=g_hall[((size_t)(0*NL+l)*NB+b)*NH+j]+g_hall[((size_t)(1*NL+l)*NB+b)*NH+j];
    g_x[((size_t)b*NL+l)*NH+j]=v;
    float n2=v*v;
    n2+=__shfl_xor_sync(0xffffffffu,n2,1);
    n2+=__shfl_xor_sync(0xffffffffu,n2,2);
    n2+=__shfl_xor_sync(0xffffffffu,n2,4);
    n2+=__shfl_xor_sync(0xffffffffu,n2,8);
    float f=(n2/(1.f+n2))*rsqrtf(n2+1e-9f);
    g_u[((size_t)b*NCAP+l*16)*16+j]=v*f;
}

// 5) entity gather + attention softmax over L
__global__ __launch_bounds__(256) void k_att(const int* __restrict__ pos1,
                                             const int* __restrict__ pos2){
    __shared__ int se1,se2;
    __shared__ float she[NH];
    __shared__ float sd[NL];
    int b=blockIdx.x, tid=threadIdx.x;
    if(tid<NL){
        if(pos1[b*NL+tid]==68) se1=tid;
        if(pos2[b*NL+tid]==68) se2=tid;
    }
    __syncthreads();
    she[tid]=g_x[((size_t)b*NL+se1)*NH+tid]+g_x[((size_t)b*NL+se2)*NH+tid];
    __syncthreads();
    int warp=tid>>5, lane=tid&31;
    for(int l=warp;l<NL;l+=8){
        const float* xr=g_x+((size_t)b*NL+l)*NH;
        float s=0.f;
        for(int k=lane;k<NH;k+=32) s+=xr[k]*she[k];
        for(int m=16;m;m>>=1) s+=__shfl_xor_sync(0xffffffffu,s,m);
        if(lane==0) sd[l]=s;
    }
    __syncthreads();
    if(tid<32){
        float vals[4],mx=-1e30f;
        #pragma unroll
        for(int q=0;q<4;q++){
            int l=tid+32*q;
            vals[q]=(l<NL)?sd[l]:-1e30f;
            mx=fmaxf(mx,vals[q]);
        }
        for(int m=16;m;m>>=1) mx=fmaxf(mx,__shfl_xor_sync(0xffffffffu,mx,m));
        float es[4],ss=0.f;
        #pragma unroll
        for(int q=0;q<4;q++){
            int l=tid+32*q;
            es[q]=(l<NL)?expf(vals[q]-mx):0.f;
            ss+=es[q];
        }
        for(int m=16;m;m>>=1) ss+=__shfl_xor_sync(0xffffffffu,ss,m);
        float inv=1.f/ss;
        #pragma unroll
        for(int q=0;q<4;q++){
            int l=tid+32*q;
            if(l<NL) g_att[b*NL+l]=es[q]*inv;
        }
    }
}

// 6) softmax(b_route) once (iter-0 coupling, batch-independent)
__global__ void k_cbase(const float* __restrict__ br){
    int i=blockIdx.x, lane=threadIdx.x;
    float v=(lane<NCL)?br[i*NCL+lane]:-1e30f;
    float mx=v;
    for(int m=16;m;m>>=1) mx=fmaxf(mx,__shfl_xor_sync(0xffffffffu,mx,m));
    float e=(lane<NCL)?expf(v-mx):0.f;
    float s=e;
    for(int m=16;m;m>>=1) s+=__shfl_xor_sync(0xffffffffu,s,m);
    if(lane<NCL) g_cbase[i*NCL+lane]=e/s;
}

// 7) u_hat[b][i][:] = u[b][i][:16] @ W_caps[i]   (1600 blocks)
__global__ __launch_bounds__(256) void k_uhat(const float* __restrict__ Wc){
    __shared__ float Ws[16*NOD];
    __shared__ float Ut[16*132];
    int i=blockIdx.x, tid=threadIdx.x;
    const float* wp=Wc+(size_t)i*16*NOD;
    for(int e=tid;e<16*NOD;e+=256) Ws[e]=wp[e];
    for(int e=tid;e<2048;e+=256){
        int bb_=e>>4,cc=e&15;
        Ut[cc*132+bb_]=g_u[((size_t)bb_*NCAP+i)*16+cc];
    }
    __syncthreads();
    for(int tI=tid;tI<32*76;tI+=256){
        int ot=tI%76, bt=tI/76, o0=ot*4, b0=bt*4;
        float acc[4][4];
        #pragma unroll
        for(int x=0;x<4;x++)
            #pragma unroll
            for(int y=0;y<4;y++) acc[x][y]=0.f;
        #pragma unroll
        for(int cc=0;cc<16;cc++){
            float4 u4=*(const float4*)(Ut+cc*132+b0);
            float4 w4=*(const float4*)(Ws+cc*NOD+o0);
            acc[0][0]+=u4.x*w4.x; acc[0][1]+=u4.x*w4.y; acc[0][2]+=u4.x*w4.z; acc[0][3]+=u4.x*w4.w;
            acc[1][0]+=u4.y*w4.x; acc[1][1]+=u4.y*w4.y; acc[1][2]+=u4.y*w4.z; acc[1][3]+=u4.y*w4.w;
            acc[2][0]+=u4.z*w4.x; acc[2][1]+=u4.z*w4.y; acc[2][2]+=u4.z*w4.z; acc[2][3]+=u4.z*w4.w;
            acc[3][0]+=u4.w*w4.x; acc[3][1]+=u4.w*w4.y; acc[3][2]+=u4.w*w4.z; acc[3][3]+=u4.w*w4.w;
        }
        #pragma unroll
        for(int bi=0;bi<4;bi++){
            float4 r4=make_float4(acc[bi][0],acc[bi][1],acc[bi][2],acc[bi][3]);
            *(float4*)(g_uhat+((size_t)(b0+bi)*NCAP+i)*NOD+o0)=r4;
        }
    }
}

// 8) fused routing pass: agreement of prev iter + weighted-sum of this iter
__global__ __launch_bounds__(320) void k_route(int mode,const float* __restrict__ b_route){
    __shared__ float sv[320];
    __shared__ float sag[32];
    __shared__ float sc[32];
    int tid=threadIdx.x, b=blockIdx.y, chunk=blockIdx.x;
    int o=tid>>4, d=tid&15;
    sv[tid]=(mode>0&&tid<NOD)?g_v[b*NOD+tid]:0.f;
    __syncthreads();
    int i0=chunk*(NCAP/NCH);
    float accS=0.f;
    float u=(tid<NOD)?g_uhat[((size_t)b*NCAP+i0)*NOD+tid]:0.f;
    for(int ii=0;ii<NCAP/NCH;ii++){
        int i=i0+ii;
        float unext=0.f;
        if(ii+1<NCAP/NCH&&tid<NOD)
            unext=g_uhat[((size_t)b*NCAP+i+1)*NOD+tid];
        float atti=g_att[b*NL+(i>>4)];
        float cO;
        if(mode==0){
            cO=(o<NCL)?g_cbase[i*NCL+o]*atti:0.f;
        } else {
            float p=u*sv[tid];
            p+=__shfl_xor_sync(0xffffffffu,p,1);
            p+=__shfl_xor_sync(0xffffffffu,p,2);
            p+=__shfl_xor_sync(0xffffffffu,p,4);
            p+=__shfl_xor_sync(0xffffffffu,p,8);
            if(d==0&&o<NCL){
                float prior=(mode==1)?b_route[i*NCL+o]:g_bb[((size_t)b*NCAP+i)*NCL+o];
                float nb=prior+p;
                if(mode==1) g_bb[((size_t)b*NCAP+i)*NCL+o]=nb;
                sag[o]=nb;
            }
            __syncthreads();
            if(tid<32){
                float v=(tid<NCL)?sag[tid]:-1e30f;
                float mx=v;
                for(int m=16;m;m>>=1) mx=fmaxf(mx,__shfl_xor_sync(0xffffffffu,mx,m));
                float e=(tid<NCL)?expf(v-mx):0.f;
                float ss=e;
                for(int m=16;m;m>>=1) ss+=__shfl_xor_sync(0xffffffffu,ss,m);
                if(tid<NCL) sc[tid]=e/ss*atti;
            }
            __syncthreads();
            cO=(o<NCL)?sc[o]:0.f;
        }
        accS+=cO*u;
        u=unext;
    }
    if(tid<NOD) g_spart[(b*NCH+chunk)*NOD+tid]=accS;
}

// 9) reduce partials + squash -> v (or final class lengths)
__global__ __launch_bounds__(320) void k_reduce(int final_out,float* __restrict__ out){
    int b=blockIdx.x, tid=threadIdx.x;
    float s=0.f;
    if(tid<NOD){
        #pragma unroll
        for(int ch=0;ch<NCH;ch++) s+=g_spart[(b*NCH+ch)*NOD+tid];
    }
    float n2=s*s;
    n2+=__shfl_xor_sync(0xffffffffu,n2,1);
    n2+=__shfl_xor_sync(0xffffffffu,n2,2);
    n2+=__shfl_xor_sync(0xffffffffu,n2,4);
    n2+=__shfl_xor_sync(0xffffffffu,n2,8);
    float f=(n2/(1.f+n2))*rsqrtf(n2+1e-9f);
    if(!final_out){
        if(tid<NOD) g_v[b*NOD+tid]=s*f;
    } else {
        if(tid<NOD&&(tid&15)==0)
            out[b*NCL+(tid>>4)]=sqrtf(n2*f*f+1e-9f);
    }
}

extern "C" void kernel_launch(void* const* d_in,const int* in_sizes,int n_in,
                              void* d_out,int out_size){
    (void)in_sizes;(void)n_in;(void)out_size;
    const int*   word =(const int*)d_in[0];
    const int*   tag  =(const int*)d_in[1];
    const int*   pos1 =(const int*)d_in[2];
    const int*   pos2 =(const int*)d_in[3];
    const float* we   =(const float*)d_in[4];
    const float* te   =(const float*)d_in[5];
    const float* p1e  =(const float*)d_in[6];
    const float* p2e  =(const float*)d_in[7];
    const float* wih_f=(const float*)d_in[8];
    const float* whh_f=(const float*)d_in[9];
    const float* bih_f=(const float*)d_in[10];
    const float* bhh_f=(const float*)d_in[11];
    const float* wih_b=(const float*)d_in[12];
    const float* whh_b=(const float*)d_in[13];
    const float* bih_b=(const float*)d_in[14];
    const float* bhh_b=(const float*)d_in[15];
    const float* Wc   =(const float*)d_in[16];
    const float* br   =(const float*)d_in[17];
    float* out=(float*)d_out;

    k_embed<<<NL*NB,160>>>(word,tag,pos1,pos2,we,te,p1e,p2e);
    k_cbase<<<NCAP,32>>>(br);
    k_xg<<<dim3(32,NL,2),256>>>(wih_f,wih_b,bih_f,bhh_f,bih_b,bhh_b);
    k_lstm<<<256,128>>>(whh_f,whh_b);
    k_combine<<<NB*NL,256>>>();
    k_att<<<NB,256>>>(pos1,pos2);
    k_uhat<<<NCAP,256>>>(Wc);
    k_route<<<dim3(NCH,NB),320>>>(0,br);
    k_reduce<<<NB,320>>>(0,out);
    k_route<<<dim3(NCH,NB),320>>>(1,br);
    k_reduce<<<NB,320>>>(0,out);
    k_route<<<dim3(NCH,NB),320>>>(2,br);
    k_reduce<<<NB,320>>>(1,out);
}

// round 8
// speedup vs baseline: 1.3598x; 1.0021x over previous
#include <cuda_runtime.h>
#include <math.h>

#define NB 128
#define NL 100
#define NH 256
#define NIN 160
#define NG 1024
#define NCAP 1600
#define NCL 19
#define NOD 304
#define NCH 8

typedef unsigned long long ull;

// packed fp32x2 fma: c = a*b + c
#define FMA2(c,a,b) asm("fma.rn.f32x2 %0, %1, %2, %3;" : "=l"(c) : "l"(a), "l"(b), "l"(c))

__device__ __forceinline__ float unpack_sum(ull v){
    float lo, hi;
    asm("mov.b64 {%0,%1}, %2;" : "=f"(lo), "=f"(hi) : "l"(v));
    return lo + hi;
}

// ---------------- static device scratch (no allocations) ----------------
__device__ float g_emb[NL*NB*NIN];
__device__ float g_xg[2*NL*NG*NB];          // [dir][t][g][b]
__device__ float g_h[2][2][NB*NH];          // ping-pong h per dir
__device__ float g_hall[2*NL*NB*NH];        // [dir][t][b][256]
__device__ float g_x[NB*NL*NH];
__device__ float g_u[NB*NCAP*16];
__device__ float g_att[NB*NL];
__device__ float g_cbase[NCAP*NCL];
__device__ float g_uhat[(size_t)NB*NCAP*NOD];
__device__ float g_bb[(size_t)NB*NCAP*NCL];
__device__ float g_spart[NB*NCH*NOD];
__device__ float g_v[NB*NOD];
// barrier words padded onto separate L2 lines AND separate slices (4KB apart):
// polling the phase must not contend with arrival atomics on the counter.
__device__ unsigned g_cnt_pad[1024];        // use [0]
__device__ unsigned g_phase_pad[1024];      // use [0]

__device__ __forceinline__ float sigm(float x){ return 1.f/(1.f+expf(-x)); }

// 1) embedding gather
__global__ void k_embed(const int* __restrict__ word,const int* __restrict__ tag,
                        const int* __restrict__ p1,const int* __restrict__ p2,
                        const float* __restrict__ we,const float* __restrict__ te,
                        const float* __restrict__ p1e,const float* __restrict__ p2e){
    int bl=blockIdx.x, t=bl/NB, b=bl%NB, d=threadIdx.x;
    float v;
    if(d<100)      v=we[(size_t)word[b*NL+t]*100+d];
    else if(d<120) v=te[tag[b*NL+t]*20+(d-100)];
    else if(d<140) v=p1e[p1[b*NL+t]*20+(d-120)];
    else           v=p2e[p2[b*NL+t]*20+(d-140)];
    g_emb[(t*NB+b)*NIN+d]=v;
}

// 2) xg = emb @ w_ih^T + b_ih + b_hh  -> [dir][t][g][b]   (R5 scalar version, known good)
__global__ __launch_bounds__(256) void k_xg(
        const float* __restrict__ wih_f,const float* __restrict__ wih_b,
        const float* __restrict__ bih_f,const float* __restrict__ bhh_f,
        const float* __restrict__ bih_b,const float* __restrict__ bhh_b){
    __shared__ float Ws[64*17];
    __shared__ float Es[64*17];
    int t=blockIdx.y, dir=blockIdx.z;
    int g0=(blockIdx.x&15)*64, b0=(blockIdx.x>>4)*64;
    const float* wih=dir?wih_b:wih_f;
    const float* bih=dir?bih_b:bih_f;
    const float* bhh=dir?bhh_b:bhh_f;
    int tid=threadIdx.x, tx=tid&15, ty=tid>>4;
    float acc[4][4];
    #pragma unroll
    for(int i=0;i<4;i++)
        #pragma unroll
        for(int j=0;j<4;j++) acc[i][j]=0.f;
    for(int kk=0;kk<NIN;kk+=16){
        #pragma unroll
        for(int e=tid;e<1024;e+=256){
            int r=e>>4,c=e&15;
            Ws[r*17+c]=wih[(g0+r)*NIN+kk+c];
            Es[r*17+c]=g_emb[(t*NB+b0+r)*NIN+kk+c];
        }
        __syncthreads();
        #pragma unroll
        for(int k=0;k<16;k++){
            float a[4],eb[4];
            #pragma unroll
            for(int i=0;i<4;i++) a[i]=Ws[(ty*4+i)*17+k];
            #pragma unroll
            for(int j=0;j<4;j++) eb[j]=Es[(tx*4+j)*17+k];
            #pragma unroll
            for(int i=0;i<4;i++)
                #pragma unroll
                for(int j=0;j<4;j++) acc[i][j]+=a[i]*eb[j];
        }
        __syncthreads();
    }
    #pragma unroll
    for(int i=0;i<4;i++){
        int g=g0+ty*4+i;
        float bias=bih[g]+bhh[g];
        float4 r4=make_float4(acc[i][0]+bias,acc[i][1]+bias,acc[i][2]+bias,acc[i][3]+bias);
        *(float4*)(g_xg+((size_t)(dir*NL+t)*NG+g)*NB+b0+tx*4)=r4;
    }
}

// 3) persistent BiLSTM: 256 CTAs x 128 threads (2 CTAs/SM, 2 hidden units/CTA),
//    f32x2 math, 8-deep LDG prefetch of h, xg prefetched ahead of the barrier,
//    grid barrier on PADDED counter/phase lines (no false sharing).
__global__ __launch_bounds__(128,2) void k_lstm(const float* __restrict__ whh_f,
                                                const float* __restrict__ whh_b){
    __shared__ __align__(16) float sW[8*256];   // 8 gate rows: (gate=r>>1, unit=u0+(r&1))
    __shared__ unsigned s_base;
    int tid=threadIdx.x;
    int dir=blockIdx.x>>7;                      // 0..127 -> dir0, 128..255 -> dir1
    int u0=(blockIdx.x&127)*2;
    const float* whh=dir?whh_b:whh_f;
    for(int e=tid;e<2048;e+=128){
        int r=e>>8,k=e&255;
        sW[e]=whh[((r>>1)*256+u0+(r&1))*256+k];
    }
    if(tid==0) s_base=*((volatile unsigned*)&g_phase_pad[0]);
    __syncthreads();
    int b=tid;
    float cst[2]={0.f,0.f};
    // prefetch xg for step 0
    float xr[8];
    {
        int t0=dir?(NL-1):0;
        const float* xgp=g_xg+((size_t)(dir*NL+t0)*NG)*NB+b;
        #pragma unroll
        for(int r=0;r<8;r++) xr[r]=__ldcg(xgp+(size_t)((r>>1)*256+u0+(r&1))*NB);
    }
    for(int s=0;s<NL;s++){
        int t=dir?(NL-1-s):s;
        ull acc2[8]={0,0,0,0,0,0,0,0};
        if(s>0){
            const float* hrow=g_h[dir][s&1]+b*NH;
            for(int kc=0;kc<256;kc+=32){
                ulonglong2 hbuf[8];
                #pragma unroll
                for(int q=0;q<8;q++)
                    hbuf[q]=__ldcg((const ulonglong2*)(hrow+kc+q*4));   // 8 LDG.128 in flight
                #pragma unroll
                for(int q=0;q<8;q++){
                    #pragma unroll
                    for(int r=0;r<8;r++){
                        const ulonglong2* w2=(const ulonglong2*)(sW+r*256+kc+q*4);
                        FMA2(acc2[r],hbuf[q].x,w2->x);
                        FMA2(acc2[r],hbuf[q].y,w2->y);
                    }
                }
            }
        }
        float acc[8];
        #pragma unroll
        for(int r=0;r<8;r++) acc[r]=unpack_sum(acc2[r])+xr[r];
        float* hdst=g_h[dir][(s+1)&1];
        float* hall=g_hall+((size_t)(dir*NL+t)*NB+b)*NH;
        #pragma unroll
        for(int j=0;j<2;j++){
            float cn=sigm(acc[2+j])*cst[j]+sigm(acc[j])*tanhf(acc[4+j]);
            cst[j]=cn;
            float hn=sigm(acc[6+j])*tanhf(cn);
            hdst[b*NH+u0+j]=hn;
            hall[u0+j]=hn;
        }
        // prefetch xg for step s+1 (h-independent) before the fence/barrier
        if(s<NL-1){
            int tn=dir?(NL-2-s):(s+1);
            const float* xgp=g_xg+((size_t)(dir*NL+tn)*NG)*NB+b;
            #pragma unroll
            for(int r=0;r<8;r++) xr[r]=__ldcg(xgp+(size_t)((r>>1)*256+u0+(r&1))*NB);
        }
        __threadfence();
        __syncthreads();
        if(tid==0){
            unsigned tgt=s_base+(unsigned)(s+1);
            if(atomicAdd(&g_cnt_pad[0],1u)==255u){
                atomicExch(&g_cnt_pad[0],0u);
                __threadfence();
                atomicAdd(&g_phase_pad[0],1u);
            } else {
                while(*((volatile unsigned*)&g_phase_pad[0]) < tgt) __nanosleep(32);
            }
        }
        __syncthreads();
    }
}

// 4) x = hf + hb ; u = squash(primary caps)
__global__ __launch_bounds__(256) void k_combine(){
    int bl=blockIdx.x, b=bl/NL, l=bl%NL, j=threadIdx.x;
    float v=g_hall[((size_t)(0*NL+l)*NB+b)*NH+j]+g_hall[((size_t)(1*NL+l)*NB+b)*NH+j];
    g_x[((size_t)b*NL+l)*NH+j]=v;
    float n2=v*v;
    n2+=__shfl_xor_sync(0xffffffffu,n2,1);
    n2+=__shfl_xor_sync(0xffffffffu,n2,2);
    n2+=__shfl_xor_sync(0xffffffffu,n2,4);
    n2+=__shfl_xor_sync(0xffffffffu,n2,8);
    float f=(n2/(1.f+n2))*rsqrtf(n2+1e-9f);
    g_u[((size_t)b*NCAP+l*16)*16+j]=v*f;
}

// 5) entity gather + attention softmax over L
__global__ __launch_bounds__(256) void k_att(const int* __restrict__ pos1,
                                             const int* __restrict__ pos2){
    __shared__ int se1,se2;
    __shared__ float she[NH];
    __shared__ float sd[NL];
    int b=blockIdx.x, tid=threadIdx.x;
    if(tid<NL){
        if(pos1[b*NL+tid]==68) se1=tid;
        if(pos2[b*NL+tid]==68) se2=tid;
    }
    __syncthreads();
    she[tid]=g_x[((size_t)b*NL+se1)*NH+tid]+g_x[((size_t)b*NL+se2)*NH+tid];
    __syncthreads();
    int warp=tid>>5, lane=tid&31;
    for(int l=warp;l<NL;l+=8){
        const float* xr=g_x+((size_t)b*NL+l)*NH;
        float s=0.f;
        for(int k=lane;k<NH;k+=32) s+=xr[k]*she[k];
        for(int m=16;m;m>>=1) s+=__shfl_xor_sync(0xffffffffu,s,m);
        if(lane==0) sd[l]=s;
    }
    __syncthreads();
    if(tid<32){
        float vals[4],mx=-1e30f;
        #pragma unroll
        for(int q=0;q<4;q++){
            int l=tid+32*q;
            vals[q]=(l<NL)?sd[l]:-1e30f;
            mx=fmaxf(mx,vals[q]);
        }
        for(int m=16;m;m>>=1) mx=fmaxf(mx,__shfl_xor_sync(0xffffffffu,mx,m));
        float es[4],ss=0.f;
        #pragma unroll
        for(int q=0;q<4;q++){
            int l=tid+32*q;
            es[q]=(l<NL)?expf(vals[q]-mx):0.f;
            ss+=es[q];
        }
        for(int m=16;m;m>>=1) ss+=__shfl_xor_sync(0xffffffffu,ss,m);
        float inv=1.f/ss;
        #pragma unroll
        for(int q=0;q<4;q++){
            int l=tid+32*q;
            if(l<NL) g_att[b*NL+l]=es[q]*inv;
        }
    }
}

// 6) softmax(b_route) once (iter-0 coupling, batch-independent)
__global__ void k_cbase(const float* __restrict__ br){
    int i=blockIdx.x, lane=threadIdx.x;
    float v=(lane<NCL)?br[i*NCL+lane]:-1e30f;
    float mx=v;
    for(int m=16;m;m>>=1) mx=fmaxf(mx,__shfl_xor_sync(0xffffffffu,mx,m));
    float e=(lane<NCL)?expf(v-mx):0.f;
    float s=e;
    for(int m=16;m;m>>=1) s+=__shfl_xor_sync(0xffffffffu,s,m);
    if(lane<NCL) g_cbase[i*NCL+lane]=e/s;
}

// 7) u_hat[b][i][:] = u[b][i][:16] @ W_caps[i]   (1600 blocks)
__global__ __launch_bounds__(256) void k_uhat(const float* __restrict__ Wc){
    __shared__ float Ws[16*NOD];
    __shared__ float Ut[16*132];
    int i=blockIdx.x, tid=threadIdx.x;
    const float* wp=Wc+(size_t)i*16*NOD;
    for(int e=tid;e<16*NOD;e+=256) Ws[e]=wp[e];
    for(int e=tid;e<2048;e+=256){
        int bb_=e>>4,cc=e&15;
        Ut[cc*132+bb_]=g_u[((size_t)bb_*NCAP+i)*16+cc];
    }
    __syncthreads();
    for(int tI=tid;tI<32*76;tI+=256){
        int ot=tI%76, bt=tI/76, o0=ot*4, b0=bt*4;
        float acc[4][4];
        #pragma unroll
        for(int x=0;x<4;x++)
            #pragma unroll
            for(int y=0;y<4;y++) acc[x][y]=0.f;
        #pragma unroll
        for(int cc=0;cc<16;cc++){
            float4 u4=*(const float4*)(Ut+cc*132+b0);
            float4 w4=*(const float4*)(Ws+cc*NOD+o0);
            acc[0][0]+=u4.x*w4.x; acc[0][1]+=u4.x*w4.y; acc[0][2]+=u4.x*w4.z; acc[0][3]+=u4.x*w4.w;
            acc[1][0]+=u4.y*w4.x; acc[1][1]+=u4.y*w4.y; acc[1][2]+=u4.y*w4.z; acc[1][3]+=u4.y*w4.w;
            acc[2][0]+=u4.z*w4.x; acc[2][1]+=u4.z*w4.y; acc[2][2]+=u4.z*w4.z; acc[2][3]+=u4.z*w4.w;
            acc[3][0]+=u4.w*w4.x; acc[3][1]+=u4.w*w4.y; acc[3][2]+=u4.w*w4.z; acc[3][3]+=u4.w*w4.w;
        }
        #pragma unroll
        for(int bi=0;bi<4;bi++){
            float4 r4=make_float4(acc[bi][0],acc[bi][1],acc[bi][2],acc[bi][3]);
            *(float4*)(g_uhat+((size_t)(b0+bi)*NCAP+i)*NOD+o0)=r4;
        }
    }
}

// 8) fused routing pass: agreement of prev iter + weighted-sum of this iter
__global__ __launch_bounds__(320) void k_route(int mode,const float* __restrict__ b_route){
    __shared__ float sv[320];
    __shared__ float sag[32];
    __shared__ float sc[32];
    int tid=threadIdx.x, b=blockIdx.y, chunk=blockIdx.x;
    int o=tid>>4, d=tid&15;
    sv[tid]=(mode>0&&tid<NOD)?g_v[b*NOD+tid]:0.f;
    __syncthreads();
    int i0=chunk*(NCAP/NCH);
    float accS=0.f;
    float u=(tid<NOD)?g_uhat[((size_t)b*NCAP+i0)*NOD+tid]:0.f;
    for(int ii=0;ii<NCAP/NCH;ii++){
        int i=i0+ii;
        float unext=0.f;
        if(ii+1<NCAP/NCH&&tid<NOD)
            unext=g_uhat[((size_t)b*NCAP+i+1)*NOD+tid];
        float atti=g_att[b*NL+(i>>4)];
        float cO;
        if(mode==0){
            cO=(o<NCL)?g_cbase[i*NCL+o]*atti:0.f;
        } else {
            float p=u*sv[tid];
            p+=__shfl_xor_sync(0xffffffffu,p,1);
            p+=__shfl_xor_sync(0xffffffffu,p,2);
            p+=__shfl_xor_sync(0xffffffffu,p,4);
            p+=__shfl_xor_sync(0xffffffffu,p,8);
            if(d==0&&o<NCL){
                float prior=(mode==1)?b_route[i*NCL+o]:g_bb[((size_t)b*NCAP+i)*NCL+o];
                float nb=prior+p;
                if(mode==1) g_bb[((size_t)b*NCAP+i)*NCL+o]=nb;
                sag[o]=nb;
            }
            __syncthreads();
            if(tid<32){
                float v=(tid<NCL)?sag[tid]:-1e30f;
                float mx=v;
                for(int m=16;m;m>>=1) mx=fmaxf(mx,__shfl_xor_sync(0xffffffffu,mx,m));
                float e=(tid<NCL)?expf(v-mx):0.f;
                float ss=e;
                for(int m=16;m;m>>=1) ss+=__shfl_xor_sync(0xffffffffu,ss,m);
                if(tid<NCL) sc[tid]=e/ss*atti;
            }
            __syncthreads();
            cO=(o<NCL)?sc[o]:0.f;
        }
        accS+=cO*u;
        u=unext;
    }
    if(tid<NOD) g_spart[(b*NCH+chunk)*NOD+tid]=accS;
}

// 9) reduce partials + squash -> v (or final class lengths)
__global__ __launch_bounds__(320) void k_reduce(int final_out,float* __restrict__ out){
    int b=blockIdx.x, tid=threadIdx.x;
    float s=0.f;
    if(tid<NOD){
        #pragma unroll
        for(int ch=0;ch<NCH;ch++) s+=g_spart[(b*NCH+ch)*NOD+tid];
    }
    float n2=s*s;
    n2+=__shfl_xor_sync(0xffffffffu,n2,1);
    n2+=__shfl_xor_sync(0xffffffffu,n2,2);
    n2+=__shfl_xor_sync(0xffffffffu,n2,4);
    n2+=__shfl_xor_sync(0xffffffffu,n2,8);
    float f=(n2/(1.f+n2))*rsqrtf(n2+1e-9f);
    if(!final_out){
        if(tid<NOD) g_v[b*NOD+tid]=s*f;
    } else {
        if(tid<NOD&&(tid&15)==0)
            out[b*NCL+(tid>>4)]=sqrtf(n2*f*f+1e-9f);
    }
}

extern "C" void kernel_launch(void* const* d_in,const int* in_sizes,int n_in,
                              void* d_out,int out_size){
    (void)in_sizes;(void)n_in;(void)out_size;
    const int*   word =(const int*)d_in[0];
    const int*   tag  =(const int*)d_in[1];
    const int*   pos1 =(const int*)d_in[2];
    const int*   pos2 =(const int*)d_in[3];
    const float* we   =(const float*)d_in[4];
    const float* te   =(const float*)d_in[5];
    const float* p1e  =(const float*)d_in[6];
    const float* p2e  =(const float*)d_in[7];
    const float* wih_f=(const float*)d_in[8];
    const float* whh_f=(const float*)d_in[9];
    const float* bih_f=(const float*)d_in[10];
    const float* bhh_f=(const float*)d_in[11];
    const float* wih_b=(const float*)d_in[12];
    const float* whh_b=(const float*)d_in[13];
    const float* bih_b=(const float*)d_in[14];
    const float* bhh_b=(const float*)d_in[15];
    const float* Wc   =(const float*)d_in[16];
    const float* br   =(const float*)d_in[17];
    float* out=(float*)d_out;

    k_embed<<<NL*NB,160>>>(word,tag,pos1,pos2,we,te,p1e,p2e);
    k_cbase<<<NCAP,32>>>(br);
    k_xg<<<dim3(32,NL,2),256>>>(wih_f,wih_b,bih_f,bhh_f,bih_b,bhh_b);
    k_lstm<<<256,128>>>(whh_f,whh_b);
    k_combine<<<NB*NL,256>>>();
    k_att<<<NB,256>>>(pos1,pos2);
    k_uhat<<<NCAP,256>>>(Wc);
    k_route<<<dim3(NCH,NB),320>>>(0,br);
    k_reduce<<<NB,320>>>(0,out);
    k_route<<<dim3(NCH,NB),320>>>(1,br);
    k_reduce<<<NB,320>>>(0,out);
    k_route<<<dim3(NCH,NB),320>>>(2,br);
    k_reduce<<<NB,320>>>(1,out);
}

// round 9
// speedup vs baseline: 1.8981x; 1.3959x over previous
#include <cuda_runtime.h>
#include <math.h>

#define NB 128
#define NL 100
#define NH 256
#define NIN 160
#define NG 1024
#define NCAP 1600
#define NCL 19
#define NOD 304
#define NCH 8
#define GSZ 8      // CTAs per LSTM group (hidden split)
#define GB  16     // batch rows per group
#define LSTM_SMEM (131072 + 16*260*4)

typedef unsigned long long ull;

// packed fp32x2 fma: c = a*b + c
#define FMA2(c,a,b) asm("fma.rn.f32x2 %0, %1, %2, %3;" : "=l"(c) : "l"(a), "l"(b), "l"(c))

__device__ __forceinline__ float unpack_sum(ull v){
    float lo, hi;
    asm("mov.b64 {%0,%1}, %2;" : "=f"(lo), "=f"(hi) : "l"(v));
    return lo + hi;
}

// ---------------- static device scratch (no allocations) ----------------
__device__ float g_emb[NL*NB*NIN];
__device__ float g_xg[2*NL*NG*NB];          // [dir][t][g][b]
__device__ float g_hx[2*8*2*256*GB];        // [dir][grp][parity][u][b16] exchange buffers
__device__ float g_hall[2*NL*NB*NH];        // [dir][t][b][256]
__device__ float g_x[NB*NL*NH];
__device__ float g_u[NB*NCAP*16];
__device__ float g_att[NB*NL];
__device__ float g_cbase[NCAP*NCL];
__device__ float g_uhat[(size_t)NB*NCAP*NOD];
__device__ float g_bb[(size_t)NB*NCAP*NCL];
__device__ float g_spart[NB*NCH*NOD];
__device__ float g_v[NB*NOD];
__device__ unsigned g_gcnt[16*64];          // per-group barrier counters, 256B apart

__device__ __forceinline__ float sigm(float x){ return 1.f/(1.f+expf(-x)); }

// 0) zero the group counters (separate launch -> race-free base for k_lstm)
__global__ void k_zero(){
    if(threadIdx.x<16) g_gcnt[threadIdx.x*64]=0u;
}

// 1) embedding gather
__global__ void k_embed(const int* __restrict__ word,const int* __restrict__ tag,
                        const int* __restrict__ p1,const int* __restrict__ p2,
                        const float* __restrict__ we,const float* __restrict__ te,
                        const float* __restrict__ p1e,const float* __restrict__ p2e){
    int bl=blockIdx.x, t=bl/NB, b=bl%NB, d=threadIdx.x;
    float v;
    if(d<100)      v=we[(size_t)word[b*NL+t]*100+d];
    else if(d<120) v=te[tag[b*NL+t]*20+(d-100)];
    else if(d<140) v=p1e[p1[b*NL+t]*20+(d-120)];
    else           v=p2e[p2[b*NL+t]*20+(d-140)];
    g_emb[(t*NB+b)*NIN+d]=v;
}

// 2) xg = emb @ w_ih^T + b_ih + b_hh  -> [dir][t][g][b]
__global__ __launch_bounds__(256) void k_xg(
        const float* __restrict__ wih_f,const float* __restrict__ wih_b,
        const float* __restrict__ bih_f,const float* __restrict__ bhh_f,
        const float* __restrict__ bih_b,const float* __restrict__ bhh_b){
    __shared__ float Ws[64*17];
    __shared__ float Es[64*17];
    int t=blockIdx.y, dir=blockIdx.z;
    int g0=(blockIdx.x&15)*64, b0=(blockIdx.x>>4)*64;
    const float* wih=dir?wih_b:wih_f;
    const float* bih=dir?bih_b:bih_f;
    const float* bhh=dir?bhh_b:bhh_f;
    int tid=threadIdx.x, tx=tid&15, ty=tid>>4;
    float acc[4][4];
    #pragma unroll
    for(int i=0;i<4;i++)
        #pragma unroll
        for(int j=0;j<4;j++) acc[i][j]=0.f;
    for(int kk=0;kk<NIN;kk+=16){
        #pragma unroll
        for(int e=tid;e<1024;e+=256){
            int r=e>>4,c=e&15;
            Ws[r*17+c]=wih[(g0+r)*NIN+kk+c];
            Es[r*17+c]=g_emb[(t*NB+b0+r)*NIN+kk+c];
        }
        __syncthreads();
        #pragma unroll
        for(int k=0;k<16;k++){
            float a[4],eb[4];
            #pragma unroll
            for(int i=0;i<4;i++) a[i]=Ws[(ty*4+i)*17+k];
            #pragma unroll
            for(int j=0;j<4;j++) eb[j]=Es[(tx*4+j)*17+k];
            #pragma unroll
            for(int i=0;i<4;i++)
                #pragma unroll
                for(int j=0;j<4;j++) acc[i][j]+=a[i]*eb[j];
        }
        __syncthreads();
    }
    #pragma unroll
    for(int i=0;i<4;i++){
        int g=g0+ty*4+i;
        float bias=bih[g]+bhh[g];
        float4 r4=make_float4(acc[i][0]+bias,acc[i][1]+bias,acc[i][2]+bias,acc[i][3]+bias);
        *(float4*)(g_xg+((size_t)(dir*NL+t)*NG+g)*NB+b0+tx*4)=r4;
    }
}

// 3) persistent BiLSTM, group-local sync.
//    16 independent groups of 8 CTAs: group = (dir, batch-slice of 16 rows).
//    Each CTA owns 32 hidden units' W_hh rows (128KB dynamic SMEM) for all 100 steps.
//    Per step: stage group h (16KB) into SMEM, matvec with f32x2, 8-arrival group barrier.
__global__ __launch_bounds__(256,1) void k_lstm(const float* __restrict__ whh_f,
                                                const float* __restrict__ whh_b){
    extern __shared__ float sm[];
    float* sW=sm;               // [lrow 0..127][k 0..255], lrow=gate*32+ul
    float* sH=sm+32768;         // [b 0..15][260]
    int tid=threadIdx.x, bid=blockIdx.x;
    int dir=bid>>6, grp=(bid>>3)&7, c=bid&7;
    int gid=dir*8+grp;
    const float* whh=dir?whh_b:whh_f;
    for(int e=tid;e<128*256;e+=256){
        int lrow=e>>8,k=e&255;
        sW[e]=whh[(size_t)((lrow>>5)*256 + c*32 + (lrow&31))*256 + k];
    }
    __syncthreads();
    int b=tid&15, usub=tid>>4;
    int bg=grp*GB+b;
    float cst[2]={0.f,0.f};
    float* hxbase=g_hx+(size_t)gid*2*256*GB;
    unsigned* cnt=&g_gcnt[gid*64];
    const float* wbase=sW+usub*512;
    // prefetch xg for step 0
    float xr[8];
    {
        int t0=dir?(NL-1):0;
        const float* xgp=g_xg+((size_t)(dir*NL+t0)*NG)*NB;
        #pragma unroll
        for(int r=0;r<8;r++){
            int g=(r>>1)*256 + c*32 + usub*2 + (r&1);
            xr[r]=__ldcg(xgp+(size_t)g*NB+bg);
        }
    }
    for(int s=0;s<NL;s++){
        int t=dir?(NL-1-s):s;
        ull acc2[8]={0,0,0,0,0,0,0,0};
        if(s>0){
            // stage h (parity s&1) into sH[b][u]
            const float* src=hxbase+(size_t)(s&1)*256*GB;
            for(int idx=tid;idx<256*GB;idx+=256)
                sH[(idx&15)*260+(idx>>4)]=__ldcg(src+idx);
            __syncthreads();
            const float* hrow=sH+b*260;
            #pragma unroll 4
            for(int k=0;k<256;k+=4){
                ulonglong2 h2=*(const ulonglong2*)(hrow+k);
                #pragma unroll
                for(int r=0;r<8;r++){
                    const ulonglong2* w2=(const ulonglong2*)(wbase+(r>>1)*8192+(r&1)*256+k);
                    FMA2(acc2[r],h2.x,w2->x);
                    FMA2(acc2[r],h2.y,w2->y);
                }
            }
        }
        float acc[8];
        #pragma unroll
        for(int r=0;r<8;r++) acc[r]=unpack_sum(acc2[r])+xr[r];
        float* hw=hxbase+(size_t)((s+1)&1)*256*GB;
        float* hall=g_hall+((size_t)(dir*NL+t)*NB+bg)*NH;
        #pragma unroll
        for(int j=0;j<2;j++){
            float cn=sigm(acc[2+j])*cst[j]+sigm(acc[j])*tanhf(acc[4+j]);
            cst[j]=cn;
            float hn=sigm(acc[6+j])*tanhf(cn);
            int u=c*32+usub*2+j;
            hw[u*GB+b]=hn;
            hall[u]=hn;
        }
        // prefetch xg for step s+1 (h-independent) before the barrier
        if(s<NL-1){
            int tn=dir?(NL-2-s):(s+1);
            const float* xgp=g_xg+((size_t)(dir*NL+tn)*NG)*NB;
            #pragma unroll
            for(int r=0;r<8;r++){
                int g=(r>>1)*256 + c*32 + usub*2 + (r&1);
                xr[r]=__ldcg(xgp+(size_t)g*NB+bg);
            }
        }
        __threadfence();
        __syncthreads();
        if(tid==0){
            atomicAdd(cnt,1u);
            if(s<NL-1){
                unsigned tgt=(unsigned)(GSZ*(s+1));
                while(*((volatile unsigned*)cnt)<tgt) __nanosleep(32);
            }
        }
        __syncthreads();
        __threadfence();
    }
}

// 4) x = hf + hb ; u = squash(primary caps)
__global__ __launch_bounds__(256) void k_combine(){
    int bl=blockIdx.x, b=bl/NL, l=bl%NL, j=threadIdx.x;
    float v=g_hall[((size_t)(0*NL+l)*NB+b)*NH+j]+g_hall[((size_t)(1*NL+l)*NB+b)*NH+j];
    g_x[((size_t)b*NL+l)*NH+j]=v;
    float n2=v*v;
    n2+=__shfl_xor_sync(0xffffffffu,n2,1);
    n2+=__shfl_xor_sync(0xffffffffu,n2,2);
    n2+=__shfl_xor_sync(0xffffffffu,n2,4);
    n2+=__shfl_xor_sync(0xffffffffu,n2,8);
    float f=(n2/(1.f+n2))*rsqrtf(n2+1e-9f);
    g_u[((size_t)b*NCAP+l*16)*16+j]=v*f;
}

// 5) entity gather + attention softmax over L
__global__ __launch_bounds__(256) void k_att(const int* __restrict__ pos1,
                                             const int* __restrict__ pos2){
    __shared__ int se1,se2;
    __shared__ float she[NH];
    __shared__ float sd[NL];
    int b=blockIdx.x, tid=threadIdx.x;
    if(tid<NL){
        if(pos1[b*NL+tid]==68) se1=tid;
        if(pos2[b*NL+tid]==68) se2=tid;
    }
    __syncthreads();
    she[tid]=g_x[((size_t)b*NL+se1)*NH+tid]+g_x[((size_t)b*NL+se2)*NH+tid];
    __syncthreads();
    int warp=tid>>5, lane=tid&31;
    for(int l=warp;l<NL;l+=8){
        const float* xr=g_x+((size_t)b*NL+l)*NH;
        float s=0.f;
        for(int k=lane;k<NH;k+=32) s+=xr[k]*she[k];
        for(int m=16;m;m>>=1) s+=__shfl_xor_sync(0xffffffffu,s,m);
        if(lane==0) sd[l]=s;
    }
    __syncthreads();
    if(tid<32){
        float vals[4],mx=-1e30f;
        #pragma unroll
        for(int q=0;q<4;q++){
            int l=tid+32*q;
            vals[q]=(l<NL)?sd[l]:-1e30f;
            mx=fmaxf(mx,vals[q]);
        }
        for(int m=16;m;m>>=1) mx=fmaxf(mx,__shfl_xor_sync(0xffffffffu,mx,m));
        float es[4],ss=0.f;
        #pragma unroll
        for(int q=0;q<4;q++){
            int l=tid+32*q;
            es[q]=(l<NL)?expf(vals[q]-mx):0.f;
            ss+=es[q];
        }
        for(int m=16;m;m>>=1) ss+=__shfl_xor_sync(0xffffffffu,ss,m);
        float inv=1.f/ss;
        #pragma unroll
        for(int q=0;q<4;q++){
            int l=tid+32*q;
            if(l<NL) g_att[b*NL+l]=es[q]*inv;
        }
    }
}

// 6) softmax(b_route) once
__global__ void k_cbase(const float* __restrict__ br){
    int i=blockIdx.x, lane=threadIdx.x;
    float v=(lane<NCL)?br[i*NCL+lane]:-1e30f;
    float mx=v;
    for(int m=16;m;m>>=1) mx=fmaxf(mx,__shfl_xor_sync(0xffffffffu,mx,m));
    float e=(lane<NCL)?expf(v-mx):0.f;
    float s=e;
    for(int m=16;m;m>>=1) s+=__shfl_xor_sync(0xffffffffu,s,m);
    if(lane<NCL) g_cbase[i*NCL+lane]=e/s;
}

// 7) u_hat[b][i][:] = u[b][i][:16] @ W_caps[i]
__global__ __launch_bounds__(256) void k_uhat(const float* __restrict__ Wc){
    __shared__ float Ws[16*NOD];
    __shared__ float Ut[16*132];
    int i=blockIdx.x, tid=threadIdx.x;
    const float* wp=Wc+(size_t)i*16*NOD;
    for(int e=tid;e<16*NOD;e+=256) Ws[e]=wp[e];
    for(int e=tid;e<2048;e+=256){
        int bb_=e>>4,cc=e&15;
        Ut[cc*132+bb_]=g_u[((size_t)bb_*NCAP+i)*16+cc];
    }
    __syncthreads();
    for(int tI=tid;tI<32*76;tI+=256){
        int ot=tI%76, bt=tI/76, o0=ot*4, b0=bt*4;
        float acc[4][4];
        #pragma unroll
        for(int x=0;x<4;x++)
            #pragma unroll
            for(int y=0;y<4;y++) acc[x][y]=0.f;
        #pragma unroll
        for(int cc=0;cc<16;cc++){
            float4 u4=*(const float4*)(Ut+cc*132+b0);
            float4 w4=*(const float4*)(Ws+cc*NOD+o0);
            acc[0][0]+=u4.x*w4.x; acc[0][1]+=u4.x*w4.y; acc[0][2]+=u4.x*w4.z; acc[0][3]+=u4.x*w4.w;
            acc[1][0]+=u4.y*w4.x; acc[1][1]+=u4.y*w4.y; acc[1][2]+=u4.y*w4.z; acc[1][3]+=u4.y*w4.w;
            acc[2][0]+=u4.z*w4.x; acc[2][1]+=u4.z*w4.y; acc[2][2]+=u4.z*w4.z; acc[2][3]+=u4.z*w4.w;
            acc[3][0]+=u4.w*w4.x; acc[3][1]+=u4.w*w4.y; acc[3][2]+=u4.w*w4.z; acc[3][3]+=u4.w*w4.w;
        }
        #pragma unroll
        for(int bi=0;bi<4;bi++){
            float4 r4=make_float4(acc[bi][0],acc[bi][1],acc[bi][2],acc[bi][3]);
            *(float4*)(g_uhat+((size_t)(b0+bi)*NCAP+i)*NOD+o0)=r4;
        }
    }
}

// 8) fused routing pass
__global__ __launch_bounds__(320) void k_route(int mode,const float* __restrict__ b_route){
    __shared__ float sv[320];
    __shared__ float sag[32];
    __shared__ float sc[32];
    int tid=threadIdx.x, b=blockIdx.y, chunk=blockIdx.x;
    int o=tid>>4, d=tid&15;
    sv[tid]=(mode>0&&tid<NOD)?g_v[b*NOD+tid]:0.f;
    __syncthreads();
    int i0=chunk*(NCAP/NCH);
    float accS=0.f;
    float u=(tid<NOD)?g_uhat[((size_t)b*NCAP+i0)*NOD+tid]:0.f;
    for(int ii=0;ii<NCAP/NCH;ii++){
        int i=i0+ii;
        float unext=0.f;
        if(ii+1<NCAP/NCH&&tid<NOD)
            unext=g_uhat[((size_t)b*NCAP+i+1)*NOD+tid];
        float atti=g_att[b*NL+(i>>4)];
        float cO;
        if(mode==0){
            cO=(o<NCL)?g_cbase[i*NCL+o]*atti:0.f;
        } else {
            float p=u*sv[tid];
            p+=__shfl_xor_sync(0xffffffffu,p,1);
            p+=__shfl_xor_sync(0xffffffffu,p,2);
            p+=__shfl_xor_sync(0xffffffffu,p,4);
            p+=__shfl_xor_sync(0xffffffffu,p,8);
            if(d==0&&o<NCL){
                float prior=(mode==1)?b_route[i*NCL+o]:g_bb[((size_t)b*NCAP+i)*NCL+o];
                float nb=prior+p;
                if(mode==1) g_bb[((size_t)b*NCAP+i)*NCL+o]=nb;
                sag[o]=nb;
            }
            __syncthreads();
            if(tid<32){
                float v=(tid<NCL)?sag[tid]:-1e30f;
                float mx=v;
                for(int m=16;m;m>>=1) mx=fmaxf(mx,__shfl_xor_sync(0xffffffffu,mx,m));
                float e=(tid<NCL)?expf(v-mx):0.f;
                float ss=e;
                for(int m=16;m;m>>=1) ss+=__shfl_xor_sync(0xffffffffu,ss,m);
                if(tid<NCL) sc[tid]=e/ss*atti;
            }
            __syncthreads();
            cO=(o<NCL)?sc[o]:0.f;
        }
        accS+=cO*u;
        u=unext;
    }
    if(tid<NOD) g_spart[(b*NCH+chunk)*NOD+tid]=accS;
}

// 9) reduce partials + squash -> v (or final class lengths)
__global__ __launch_bounds__(320) void k_reduce(int final_out,float* __restrict__ out){
    int b=blockIdx.x, tid=threadIdx.x;
    float s=0.f;
    if(tid<NOD){
        #pragma unroll
        for(int ch=0;ch<NCH;ch++) s+=g_spart[(b*NCH+ch)*NOD+tid];
    }
    float n2=s*s;
    n2+=__shfl_xor_sync(0xffffffffu,n2,1);
    n2+=__shfl_xor_sync(0xffffffffu,n2,2);
    n2+=__shfl_xor_sync(0xffffffffu,n2,4);
    n2+=__shfl_xor_sync(0xffffffffu,n2,8);
    float f=(n2/(1.f+n2))*rsqrtf(n2+1e-9f);
    if(!final_out){
        if(tid<NOD) g_v[b*NOD+tid]=s*f;
    } else {
        if(tid<NOD&&(tid&15)==0)
            out[b*NCL+(tid>>4)]=sqrtf(n2*f*f+1e-9f);
    }
}

extern "C" void kernel_launch(void* const* d_in,const int* in_sizes,int n_in,
                              void* d_out,int out_size){
    (void)in_sizes;(void)n_in;(void)out_size;
    const int*   word =(const int*)d_in[0];
    const int*   tag  =(const int*)d_in[1];
    const int*   pos1 =(const int*)d_in[2];
    const int*   pos2 =(const int*)d_in[3];
    const float* we   =(const float*)d_in[4];
    const float* te   =(const float*)d_in[5];
    const float* p1e  =(const float*)d_in[6];
    const float* p2e  =(const float*)d_in[7];
    const float* wih_f=(const float*)d_in[8];
    const float* whh_f=(const float*)d_in[9];
    const float* bih_f=(const float*)d_in[10];
    const float* bhh_f=(const float*)d_in[11];
    const float* wih_b=(const float*)d_in[12];
    const float* whh_b=(const float*)d_in[13];
    const float* bih_b=(const float*)d_in[14];
    const float* bhh_b=(const float*)d_in[15];
    const float* Wc   =(const float*)d_in[16];
    const float* br   =(const float*)d_in[17];
    float* out=(float*)d_out;

    cudaFuncSetAttribute(k_lstm, cudaFuncAttributeMaxDynamicSharedMemorySize, LSTM_SMEM);

    k_embed<<<NL*NB,160>>>(word,tag,pos1,pos2,we,te,p1e,p2e);
    k_cbase<<<NCAP,32>>>(br);
    k_xg<<<dim3(32,NL,2),256>>>(wih_f,wih_b,bih_f,bhh_f,bih_b,bhh_b);
    k_zero<<<1,32>>>();
    k_lstm<<<128,256,LSTM_SMEM>>>(whh_f,whh_b);
    k_combine<<<NB*NL,256>>>();
    k_att<<<NB,256>>>(pos1,pos2);
    k_uhat<<<NCAP,256>>>(Wc);
    k_route<<<dim3(NCH,NB),320>>>(0,br);
    k_reduce<<<NB,320>>>(0,out);
    k_route<<<dim3(NCH,NB),320>>>(1,br);
    k_reduce<<<NB,320>>>(0,out);
    k_route<<<dim3(NCH,NB),320>>>(2,br);
    k_reduce<<<NB,320>>>(1,out);
}